// round 15
// baseline (speedup 1.0000x reference)
#include <cuda_runtime.h>
#include <cuda_fp16.h>
#include <stdint.h>
#include <math.h>

#define D_EMB   1024
#define N_BATCH 4
#define N_SEQ   2048
#define BN_TOT  (N_BATCH * N_SEQ)   // 8192

// ---------------------------------------------------------------------------
// Device scratch (allocation-free per harness rules)
// ---------------------------------------------------------------------------
__device__ __half g_xh[BN_TOT * D_EMB], g_xl[BN_TOT * D_EMB];
__device__ __half g_Wqh[D_EMB * D_EMB], g_Wql[D_EMB * D_EMB];  // plain split
__device__ __half g_Wkh[D_EMB * D_EMB], g_Wkl[D_EMB * D_EMB];  // plain split
__device__ __half g_Wvh[D_EMB * D_EMB], g_Wvl[D_EMB * D_EMB];  // transposed split
__device__ __half g_Wmh[D_EMB * D_EMB], g_Wml[D_EMB * D_EMB];  // transposed split
__device__ __half g_M2h[D_EMB * D_EMB], g_M2l[D_EMB * D_EMB];  // Wq*Wk^T
__device__ __half g_Zh[BN_TOT * D_EMB], g_Zl[BN_TOT * D_EMB];  // x*M
__device__ float g_Vf[BN_TOT * D_EMB];
__device__ __half g_Vth[BN_TOT * D_EMB], g_Vtl[BN_TOT * D_EMB];
__device__ __half g_Th[BN_TOT * D_EMB];
__device__ float g_S[(size_t)N_BATCH * N_SEQ * N_SEQ];
__device__ __half g_ah[(size_t)N_BATCH * N_SEQ * N_SEQ];   // alpha hi only
__device__ float g_wv[D_EMB];     // Wq * bk
__device__ float g_w[BN_TOT];     // x * (Wq*bk)

// ---------------------------------------------------------------------------
// static streams/events (exact R10 topology)
// ---------------------------------------------------------------------------
static cudaStream_t g_sB;
static cudaEvent_t g_e0, g_eX, g_eW, g_eV;
static struct StreamInit {
    StreamInit() {
        cudaStreamCreateWithFlags(&g_sB, cudaStreamNonBlocking);
        cudaEventCreateWithFlags(&g_e0, cudaEventDisableTiming);
        cudaEventCreateWithFlags(&g_eX, cudaEventDisableTiming);
        cudaEventCreateWithFlags(&g_eW, cudaEventDisableTiming);
        cudaEventCreateWithFlags(&g_eV, cudaEventDisableTiming);
    }
} g_stream_init;

// ---------------------------------------------------------------------------
// helpers
// ---------------------------------------------------------------------------
__device__ __forceinline__ uint32_t smem_u32(const void* p) {
    uint32_t a;
    asm("{ .reg .u64 t; cvta.to.shared.u64 t, %1; cvt.u32.u64 %0, t; }"
        : "=r"(a) : "l"(p));
    return a;
}
__device__ __forceinline__ uint64_t gptr64(const void* p) {
    uint64_t g;
    asm("cvta.to.global.u64 %0, %1;" : "=l"(g) : "l"(p));
    return g;
}
__device__ __forceinline__ void cp16(uint32_t saddr, const void* g) {
    asm volatile("cp.async.cg.shared.global [%0], [%1], 16;"
                 :: "r"(saddr), "l"(gptr64(g)) : "memory");
}

// warp-level fp16 MMA, fp32 accumulate (fallback HMMA on sm_103)
__device__ __forceinline__ void mma16816(float* c, const uint32_t* a, const uint32_t* b) {
    asm volatile(
        "mma.sync.aligned.m16n8k16.row.col.f32.f16.f16.f32 "
        "{%0,%1,%2,%3}, {%4,%5,%6,%7}, {%8,%9}, {%0,%1,%2,%3};"
        : "+f"(c[0]), "+f"(c[1]), "+f"(c[2]), "+f"(c[3])
        : "r"(a[0]), "r"(a[1]), "r"(a[2]), "r"(a[3]), "r"(b[0]), "r"(b[1]));
}
__device__ __forceinline__ void ldm_x4(uint32_t* r, uint32_t addr) {
    asm volatile("ldmatrix.sync.aligned.m8n8.x4.shared.b16 {%0,%1,%2,%3}, [%4];"
                 : "=r"(r[0]), "=r"(r[1]), "=r"(r[2]), "=r"(r[3]) : "r"(addr));
}
// NON-transposed x2: correct for B stored [N,K] row-major (K-contiguous)
__device__ __forceinline__ void ldm_x2(uint32_t* r, uint32_t addr) {
    asm volatile("ldmatrix.sync.aligned.m8n8.x2.shared.b16 {%0,%1}, [%2];"
                 : "=r"(r[0]), "=r"(r[1]) : "r"(addr));
}

__device__ __forceinline__ void split1(float v, __half& h, __half& l) {
    h = __float2half(v);
    l = __float2half(v - __half2float(h));
}
__device__ __forceinline__ uint32_t pack2(__half a, __half b) {
    __half2 t; t.x = a; t.y = b;
    return *reinterpret_cast<uint32_t*>(&t);
}

// smem geometry: rows padded to 40 fp16 (80B) -> conflict-free ldmatrix
#define KC          32
#define ROW_PAD     40
#define TILE_BYTES  (128 * ROW_PAD * 2)          // 10240 per matrix tile
#define OFF_AL      TILE_BYTES
#define OFF_BH      (2 * TILE_BYTES)
#define OFF_BL      (3 * TILE_BYTES)
#define STAGE_BYTES (4 * TILE_BYTES)             // 40960
#define N_STAGES    2
#define SMEM_BYTES  (N_STAGES * STAGE_BYTES)     // 81920 -> 2 CTAs/SM

// ---------------------------------------------------------------------------
// NT GEMM: C = (Ah+Al)[M,K] @ (Bh+Bl)[N,K]^T, fp16 split.
// NPROD=3: hh+lh+hl. NPROD=2: hh+lh. NPROD=1: hh only.
// OM=0: fp32 C. OM=1: fp16 hi/lo split. OM=2: fp16 hi only.
// BMODE=0: none. BMODE=1: column bias. BMODE=2: row bias.
// CTA 128x128, 8 warps (2x4), warp tile 64x32, 2-stage pipeline, 2 CTAs/SM.
// ---------------------------------------------------------------------------
template <int NPROD, int OM, int BMODE, bool RELU>
__global__ __launch_bounds__(256, 2)
void gemm_mma(const __half* __restrict__ Ah, const __half* __restrict__ Al,
              const __half* __restrict__ Bh, const __half* __restrict__ Bl,
              const float* __restrict__ bias, float* __restrict__ C,
              __half* __restrict__ Ch, __half* __restrict__ Cl,
              int Nn, int Kd, long long sA, long long sB, long long sC)
{
    extern __shared__ __align__(128) char smem[];
    const int tid = threadIdx.x;
    const long long z = blockIdx.z;
    Ah += z * sA;
    if (NPROD >= 2) Al += z * sA;
    Bh += z * sB;
    if (NPROD == 3) Bl += z * sB;
    const int row0 = blockIdx.y * 128;
    const int col0 = blockIdx.x * 128;

    const int warp  = tid >> 5;
    const int lane  = tid & 31;
    const int g     = lane >> 2;
    const int t     = lane & 3;
    const int mbase = (warp & 1) * 64;      // 2x4 warp grid
    const int nbase = (warp >> 1) * 32;

    const uint32_t sbase = smem_u32(smem);

    const uint32_t a_off = (uint32_t)(((mbase + (lane & 15)) * ROW_PAD + (lane >> 4) * 8) * 2);
    const uint32_t b_off = (uint32_t)(((nbase + (lane & 7)) * ROW_PAD + ((lane >> 3) & 1) * 8) * 2);

    float acc[4][4][4];
#pragma unroll
    for (int mi = 0; mi < 4; mi++)
#pragma unroll
        for (int ni = 0; ni < 4; ni++)
#pragma unroll
            for (int r = 0; r < 4; r++) acc[mi][ni][r] = 0.f;

    // per stage: A 512 cp16 (hi) + 512 (lo), B 512 (+512): 2 per thread per tile
    auto load_stage = [&](int st, int kc) {
        const uint32_t sb = sbase + (uint32_t)st * STAGE_BYTES;
        const int k0 = kc * KC;
#pragma unroll
        for (int i = 0; i < 2; i++) {
            const int idx = tid + (i << 8);
            const int r  = idx >> 2;
            const int c4 = idx & 3;
            const uint32_t soff = (uint32_t)(r * 80 + c4 * 16);
            const long long ga = (long long)(row0 + r) * Kd + k0 + c4 * 8;
            const long long gb = (long long)(col0 + r) * Kd + k0 + c4 * 8;
            cp16(sb + soff, Ah + ga);
            if (NPROD >= 2) cp16(sb + OFF_AL + soff, Al + ga);
            cp16(sb + OFF_BH + soff, Bh + gb);
            if (NPROD == 3) cp16(sb + OFF_BL + soff, Bl + gb);
        }
        asm volatile("cp.async.commit_group;" ::: "memory");
    };

    auto compute_stage = [&](int st) {
        const uint32_t sb  = sbase + (uint32_t)st * STAGE_BYTES;
        const uint32_t aoh = sb + a_off;
        const uint32_t aol = aoh + OFF_AL;
        const uint32_t boh = sb + OFF_BH + b_off;
        const uint32_t bol = boh + TILE_BYTES;
#pragma unroll
        for (int kk = 0; kk < 2; kk++) {
            uint32_t ahf[4][4], bhf[4][2];
            // hh sweep
#pragma unroll
            for (int mi = 0; mi < 4; mi++) ldm_x4(ahf[mi], aoh + mi * 1280 + kk * 32);
#pragma unroll
            for (int ni = 0; ni < 4; ni++) ldm_x2(bhf[ni], boh + ni * 640 + kk * 32);
#pragma unroll
            for (int mi = 0; mi < 4; mi++)
#pragma unroll
                for (int ni = 0; ni < 4; ni++) mma16816(acc[mi][ni], ahf[mi], bhf[ni]);
            // lh sweep (A_lo x B_hi)
            if (NPROD >= 2) {
                uint32_t alf[4][4];
#pragma unroll
                for (int mi = 0; mi < 4; mi++) ldm_x4(alf[mi], aol + mi * 1280 + kk * 32);
#pragma unroll
                for (int mi = 0; mi < 4; mi++)
#pragma unroll
                    for (int ni = 0; ni < 4; ni++) mma16816(acc[mi][ni], alf[mi], bhf[ni]);
            }
            // hl sweep (A_hi x B_lo)
            if (NPROD == 3) {
                uint32_t blf[4][2];
#pragma unroll
                for (int ni = 0; ni < 4; ni++) ldm_x2(blf[ni], bol + ni * 640 + kk * 32);
#pragma unroll
                for (int mi = 0; mi < 4; mi++)
#pragma unroll
                    for (int ni = 0; ni < 4; ni++) mma16816(acc[mi][ni], ahf[mi], blf[ni]);
            }
        }
    };

    const int nc = Kd / KC;
    load_stage(0, 0);
    load_stage(1, 1);

    for (int c = 0; c < nc; c++) {
        if (c + 2 < nc) asm volatile("cp.async.wait_group 1;" ::: "memory");
        else            asm volatile("cp.async.wait_group 0;" ::: "memory");
        __syncthreads();
        compute_stage(c & 1);
        __syncthreads();                 // compute done before overwriting stage
        if (c + 2 < nc) load_stage(c & 1, c + 2);
    }

    // ---- epilogue ----
#pragma unroll
    for (int mi = 0; mi < 4; mi++) {
        const long long r = row0 + mbase + mi * 16 + g;
        float rb0 = 0.f, rb1 = 0.f;
        if (BMODE == 2) { rb0 = bias[r]; rb1 = bias[r + 8]; }
#pragma unroll
        for (int ni = 0; ni < 4; ni++) {
            const int cc = col0 + nbase + ni * 8 + t * 2;
            float2 v0, v1;
            v0.x = acc[mi][ni][0]; v0.y = acc[mi][ni][1];
            v1.x = acc[mi][ni][2]; v1.y = acc[mi][ni][3];
            if (BMODE == 1) {
                const float2 bv = *(const float2*)(bias + cc);
                v0.x += bv.x; v0.y += bv.y;
                v1.x += bv.x; v1.y += bv.y;
            } else if (BMODE == 2) {
                v0.x += rb0; v0.y += rb0;
                v1.x += rb1; v1.y += rb1;
            }
            if (RELU) {
                v0.x = fmaxf(v0.x, 0.f); v0.y = fmaxf(v0.y, 0.f);
                v1.x = fmaxf(v1.x, 0.f); v1.y = fmaxf(v1.y, 0.f);
            }
            if (OM == 0) {
                float* Cz = C + z * sC;
                *(float2*)(Cz + r * Nn + cc)       = v0;
                *(float2*)(Cz + (r + 8) * Nn + cc) = v1;
            } else if (OM == 1) {
                __half* Chz = Ch + z * sC;
                __half* Clz = Cl + z * sC;
                __half h0, h1, l0, l1;
                split1(v0.x, h0, l0); split1(v0.y, h1, l1);
                *(uint32_t*)(Chz + r * Nn + cc) = pack2(h0, h1);
                *(uint32_t*)(Clz + r * Nn + cc) = pack2(l0, l1);
                split1(v1.x, h0, l0); split1(v1.y, h1, l1);
                *(uint32_t*)(Chz + (r + 8) * Nn + cc) = pack2(h0, h1);
                *(uint32_t*)(Clz + (r + 8) * Nn + cc) = pack2(l0, l1);
            } else {
                __half* Chz = Ch + z * sC;
                *(uint32_t*)(Chz + r * Nn + cc) =
                    pack2(__float2half(v0.x), __float2half(v0.y));
                *(uint32_t*)(Chz + (r + 8) * Nn + cc) =
                    pack2(__float2half(v1.x), __float2half(v1.y));
            }
        }
    }
}

// ---------------------------------------------------------------------------
// fp32 -> fp16 hi/lo elementwise split
// ---------------------------------------------------------------------------
__global__ __launch_bounds__(256)
void split_kernel(const float* __restrict__ in, __half* __restrict__ oh,
                  __half* __restrict__ ol, long long n4)
{
    long long i = (long long)blockIdx.x * blockDim.x + threadIdx.x;
    if (i >= n4) return;
    float4 v = ((const float4*)in)[i];
    __half h0, h1, h2, h3, l0, l1, l2, l3;
    split1(v.x, h0, l0); split1(v.y, h1, l1);
    split1(v.z, h2, l2); split1(v.w, h3, l3);
    uint2 hv, lv;
    hv.x = pack2(h0, h1); hv.y = pack2(h2, h3);
    lv.x = pack2(l0, l1); lv.y = pack2(l2, l3);
    ((uint2*)oh)[i] = hv;
    ((uint2*)ol)[i] = lv;
}

// ---------------------------------------------------------------------------
// fp32 [R,C] -> transposed fp16 hi/lo [C,R] (batched via blockIdx.z)
// ---------------------------------------------------------------------------
__global__ __launch_bounds__(256)
void tsplit_kernel(const float* __restrict__ in, __half* __restrict__ oh,
                   __half* __restrict__ ol, int R, int C)
{
    __shared__ float t[32][33];
    const long long zoff = (long long)blockIdx.z * R * C;
    in += zoff; oh += zoff; ol += zoff;
    const int tx = threadIdx.x, ty = threadIdx.y;
    const int x = blockIdx.x * 32 + tx;
    const int y0 = blockIdx.y * 32 + ty;
#pragma unroll
    for (int i = 0; i < 32; i += 8)
        t[ty + i][tx] = in[(long long)(y0 + i) * C + x];
    __syncthreads();
    const int ox = blockIdx.y * 32 + tx;
    const int oy0 = blockIdx.x * 32 + ty;
#pragma unroll
    for (int i = 0; i < 32; i += 8) {
        float v = t[tx][ty + i];
        __half h, l;
        split1(v, h, l);
        oh[(long long)(oy0 + i) * R + ox] = h;
        ol[(long long)(oy0 + i) * R + ox] = l;
    }
}

// ---------------------------------------------------------------------------
// warp-per-row matvec
// ---------------------------------------------------------------------------
__inline__ __device__ float warpSum(float v) {
#pragma unroll
    for (int o = 16; o > 0; o >>= 1) v += __shfl_xor_sync(0xffffffffu, v, o);
    return v;
}
__inline__ __device__ float warpMax(float v) {
#pragma unroll
    for (int o = 16; o > 0; o >>= 1) v = fmaxf(v, __shfl_xor_sync(0xffffffffu, v, o));
    return v;
}

__global__ __launch_bounds__(256)
void matvec_kernel(const float* __restrict__ Mrow, const float* __restrict__ v,
                   float* __restrict__ out)
{
    const int row  = blockIdx.x * 8 + (threadIdx.x >> 5);
    const int lane = threadIdx.x & 31;
    const float* R = Mrow + (long long)row * D_EMB;
    float s = 0.f;
#pragma unroll
    for (int d = lane * 4; d < D_EMB; d += 128) {
        const float4 a = *(const float4*)(R + d);
        const float4 b = *(const float4*)(v + d);
        s += a.x * b.x + a.y * b.y + a.z * b.z + a.w * b.w;
    }
    s = warpSum(s);
    if (lane == 0) out[row] = s;
}

// ---------------------------------------------------------------------------
// Row softmax over 2048 fp32 (+ per-i offset w) -> fp16 hi output only
// ---------------------------------------------------------------------------
__global__ __launch_bounds__(256)
void softmax_split(const float* __restrict__ S, const float* __restrict__ w,
                   __half* __restrict__ ah)
{
    const long long base = (long long)blockIdx.x * N_SEQ;
    const float* row = S + base;
    const float* wb  = w + (long long)(blockIdx.x >> 11) * N_SEQ;
    const int tid = threadIdx.x;
    const int lane = tid & 31;
    const int wid = tid >> 5;

    float4 v0 = ((const float4*)row)[tid];
    float4 v1 = ((const float4*)row)[tid + 256];
    const float4 w0 = ((const float4*)wb)[tid];
    const float4 w1 = ((const float4*)wb)[tid + 256];
    v0.x += w0.x; v0.y += w0.y; v0.z += w0.z; v0.w += w0.w;
    v1.x += w1.x; v1.y += w1.y; v1.z += w1.z; v1.w += w1.w;

    __shared__ float sm[8];
    float m = fmaxf(fmaxf(fmaxf(v0.x, v0.y), fmaxf(v0.z, v0.w)),
                    fmaxf(fmaxf(v1.x, v1.y), fmaxf(v1.z, v1.w)));
    m = warpMax(m);
    if (lane == 0) sm[wid] = m;
    __syncthreads();
    if (wid == 0) {
        float t = (lane < 8) ? sm[lane] : -3.402823e38f;
        t = warpMax(t);
        if (lane == 0) sm[0] = t;
    }
    __syncthreads();
    m = sm[0];
    __syncthreads();

    v0.x = expf(v0.x - m); v0.y = expf(v0.y - m);
    v0.z = expf(v0.z - m); v0.w = expf(v0.w - m);
    v1.x = expf(v1.x - m); v1.y = expf(v1.y - m);
    v1.z = expf(v1.z - m); v1.w = expf(v1.w - m);

    float s = (v0.x + v0.y + v0.z + v0.w) + (v1.x + v1.y + v1.z + v1.w);
    s = warpSum(s);
    if (lane == 0) sm[wid] = s;
    __syncthreads();
    if (wid == 0) {
        float t = (lane < 8) ? sm[lane] : 0.f;
        t = warpSum(t);
        if (lane == 0) sm[0] = t;
    }
    __syncthreads();
    const float inv = 1.0f / sm[0];

    uint2 hv;
    hv.x = pack2(__float2half(v0.x * inv), __float2half(v0.y * inv));
    hv.y = pack2(__float2half(v0.z * inv), __float2half(v0.w * inv));
    ((uint2*)(ah + base))[tid] = hv;
    hv.x = pack2(__float2half(v1.x * inv), __float2half(v1.y * inv));
    hv.y = pack2(__float2half(v1.z * inv), __float2half(v1.w * inv));
    ((uint2*)(ah + base))[tid + 256] = hv;
}

// ---------------------------------------------------------------------------
extern "C" void kernel_launch(void* const* d_in, const int* in_sizes, int n_in,
                              void* d_out, int out_size)
{
    const float* x  = (const float*)d_in[0];
    const float* Wq = (const float*)d_in[1];
    const float* bq = (const float*)d_in[2];
    const float* Wk = (const float*)d_in[3];
    const float* bk = (const float*)d_in[4];
    const float* Wv = (const float*)d_in[5];
    const float* bv = (const float*)d_in[6];
    const float* Wm = (const float*)d_in[7];
    const float* bm = (const float*)d_in[8];
    float* out = (float*)d_out;
    (void)bq;  // bq enters scores only via terms constant along the softmax axis

    __half *xh, *xl, *Wqh, *Wql, *Wkh, *Wkl, *Wvh, *Wvl, *Wmh, *Wml;
    __half *M2h, *M2l, *Zh, *Zl, *Vth, *Vtl, *Th, *ah;
    float *Vf, *S, *wv, *w;
    cudaGetSymbolAddress((void**)&xh, g_xh);   cudaGetSymbolAddress((void**)&xl, g_xl);
    cudaGetSymbolAddress((void**)&Wqh, g_Wqh); cudaGetSymbolAddress((void**)&Wql, g_Wql);
    cudaGetSymbolAddress((void**)&Wkh, g_Wkh); cudaGetSymbolAddress((void**)&Wkl, g_Wkl);
    cudaGetSymbolAddress((void**)&Wvh, g_Wvh); cudaGetSymbolAddress((void**)&Wvl, g_Wvl);
    cudaGetSymbolAddress((void**)&Wmh, g_Wmh); cudaGetSymbolAddress((void**)&Wml, g_Wml);
    cudaGetSymbolAddress((void**)&M2h, g_M2h); cudaGetSymbolAddress((void**)&M2l, g_M2l);
    cudaGetSymbolAddress((void**)&Zh, g_Zh);   cudaGetSymbolAddress((void**)&Zl, g_Zl);
    cudaGetSymbolAddress((void**)&Vf, g_Vf);
    cudaGetSymbolAddress((void**)&Vth, g_Vth); cudaGetSymbolAddress((void**)&Vtl, g_Vtl);
    cudaGetSymbolAddress((void**)&Th, g_Th);
    cudaGetSymbolAddress((void**)&ah, g_ah);
    cudaGetSymbolAddress((void**)&S, g_S);
    cudaGetSymbolAddress((void**)&wv, g_wv);   cudaGetSymbolAddress((void**)&w, g_w);

    cudaFuncSetAttribute(gemm_mma<3, 1, 0, false>,
                         cudaFuncAttributeMaxDynamicSharedMemorySize, SMEM_BYTES);
    cudaFuncSetAttribute(gemm_mma<3, 0, 0, false>,
                         cudaFuncAttributeMaxDynamicSharedMemorySize, SMEM_BYTES);
    cudaFuncSetAttribute(gemm_mma<1, 0, 1, false>,
                         cudaFuncAttributeMaxDynamicSharedMemorySize, SMEM_BYTES);
    cudaFuncSetAttribute(gemm_mma<1, 2, 0, false>,
                         cudaFuncAttributeMaxDynamicSharedMemorySize, SMEM_BYTES);
    cudaFuncSetAttribute(gemm_mma<1, 0, 1, true>,
                         cudaFuncAttributeMaxDynamicSharedMemorySize, SMEM_BYTES);

    const long long nX = (long long)BN_TOT * D_EMB;
    const long long nW = (long long)D_EMB * D_EMB;

    // ---- fork side stream (exact R10 topology) ----
    cudaEventRecord(g_e0, 0);
    cudaStreamWaitEvent(g_sB, g_e0, 0);

    // side stream: weight transposes + bias matvecs
    {
        dim3 g(D_EMB / 32, D_EMB / 32, 1), b(32, 8);
        tsplit_kernel<<<g, b, 0, g_sB>>>(Wv, Wvh, Wvl, D_EMB, D_EMB);
        tsplit_kernel<<<g, b, 0, g_sB>>>(Wm, Wmh, Wml, D_EMB, D_EMB);
    }
    matvec_kernel<<<D_EMB / 8, 256, 0, g_sB>>>(Wq, bk, wv);
    matvec_kernel<<<BN_TOT / 8, 256, 0, g_sB>>>(x, wv, w);
    cudaEventRecord(g_eW, g_sB);

    // main stream: split x
    split_kernel<<<(unsigned)((nX / 4 + 255) / 256), 256>>>(x, xh, xl, nX / 4);
    cudaEventRecord(g_eX, 0);
    cudaStreamWaitEvent(g_sB, g_eX, 0);

    // side stream (R10): V projection (1-MMA) -> fp32 Vf, then transpose-split
    {
        dim3 g(D_EMB / 128, BN_TOT / 128, 1);
        gemm_mma<1, 0, 1, false><<<g, 256, SMEM_BYTES, g_sB>>>(
            xh, nullptr, Wvh, nullptr, bv, Vf, nullptr, nullptr,
            D_EMB, D_EMB, 0, 0, 0);
        dim3 gt(D_EMB / 32, N_SEQ / 32, N_BATCH), bt(32, 8);
        tsplit_kernel<<<gt, bt, 0, g_sB>>>(Vf, Vth, Vtl, N_SEQ, D_EMB);
    }
    cudaEventRecord(g_eV, g_sB);

    // main stream: Wq/Wk splits -> M2 (monolithic) -> Z
    split_kernel<<<(unsigned)((nW / 4 + 255) / 256), 256>>>(Wq, Wqh, Wql, nW / 4);
    split_kernel<<<(unsigned)((nW / 4 + 255) / 256), 256>>>(Wk, Wkh, Wkl, nW / 4);
    {
        dim3 g(D_EMB / 128, D_EMB / 128, 1);
        gemm_mma<3, 1, 0, false><<<g, 256, SMEM_BYTES>>>(
            Wqh, Wql, Wkh, Wkl, nullptr, nullptr, M2h, M2l, D_EMB, D_EMB, 0, 0, 0);
    }
    {
        dim3 g(D_EMB / 128, BN_TOT / 128, 1);
        gemm_mma<3, 1, 0, false><<<g, 256, SMEM_BYTES>>>(
            xh, xl, M2h, M2l, nullptr, nullptr, Zh, Zl, D_EMB, D_EMB, 0, 0, 0);
    }

    // main stream: S (single batched launch)
    {
        dim3 g(N_SEQ / 128, N_SEQ / 128, N_BATCH);
        gemm_mma<3, 0, 0, false><<<g, 256, SMEM_BYTES>>>(
            Zh, Zl, xh, xl, nullptr, S, nullptr, nullptr,
            N_SEQ, D_EMB,
            (long long)N_SEQ * D_EMB, (long long)N_SEQ * D_EMB,
            (long long)N_SEQ * N_SEQ);
    }

    // softmax (needs w), T (needs Vth), out — all on main (R10 pattern)
    cudaStreamWaitEvent(0, g_eW, 0);
    softmax_split<<<BN_TOT, 256>>>(S, w, ah);

    cudaStreamWaitEvent(0, g_eV, 0);
    {
        dim3 g(D_EMB / 128, N_SEQ / 128, N_BATCH);
        gemm_mma<1, 2, 0, false><<<g, 256, SMEM_BYTES>>>(
            ah, nullptr, Vth, nullptr, nullptr, nullptr, Th, nullptr,
            D_EMB, N_SEQ,
            (long long)N_SEQ * N_SEQ, (long long)D_EMB * N_SEQ,
            (long long)N_SEQ * D_EMB);
    }
    {
        dim3 g(D_EMB / 128, BN_TOT / 128, 1);
        gemm_mma<1, 0, 1, true><<<g, 256, SMEM_BYTES>>>(
            Th, nullptr, Wmh, nullptr, bm, out, nullptr, nullptr,
            D_EMB, D_EMB, 0, 0, 0);
    }
}

// round 16
// speedup vs baseline: 1.1562x; 1.1562x over previous
#include <cuda_runtime.h>
#include <cuda_fp16.h>
#include <stdint.h>
#include <math.h>

#define D_EMB   1024
#define N_BATCH 4
#define N_SEQ   2048
#define BN_TOT  (N_BATCH * N_SEQ)   // 8192

// ---------------------------------------------------------------------------
// Device scratch (allocation-free per harness rules)
// ---------------------------------------------------------------------------
__device__ __half g_xh[BN_TOT * D_EMB], g_xl[BN_TOT * D_EMB];
__device__ __half g_Wqh[D_EMB * D_EMB], g_Wql[D_EMB * D_EMB];  // plain split
__device__ __half g_Wkh[D_EMB * D_EMB], g_Wkl[D_EMB * D_EMB];  // plain split
__device__ __half g_Wvh[D_EMB * D_EMB], g_Wvl[D_EMB * D_EMB];  // transposed split
__device__ __half g_Wmh[D_EMB * D_EMB], g_Wml[D_EMB * D_EMB];  // transposed split
__device__ __half g_M2h[D_EMB * D_EMB], g_M2l[D_EMB * D_EMB];  // Wq*Wk^T
__device__ __half g_Zh[BN_TOT * D_EMB], g_Zl[BN_TOT * D_EMB];  // x*M
__device__ float g_Vf[BN_TOT * D_EMB];
__device__ __half g_Vh[BN_TOT * D_EMB];                        // V hi, [i,d] plain
__device__ __half g_VWt[(size_t)N_BATCH * D_EMB * N_SEQ];      // (V@Wm)^T hi, [e,i]
__device__ float g_S[(size_t)N_BATCH * N_SEQ * N_SEQ];
__device__ __half g_ah[(size_t)N_BATCH * N_SEQ * N_SEQ];   // alpha hi only
__device__ float g_wv[D_EMB];     // Wq * bk
__device__ float g_w[BN_TOT];     // x * (Wq*bk)

// ---------------------------------------------------------------------------
// static streams/events (exact R10 topology)
// ---------------------------------------------------------------------------
static cudaStream_t g_sB;
static cudaEvent_t g_e0, g_eX, g_eW, g_eV;
static struct StreamInit {
    StreamInit() {
        cudaStreamCreateWithFlags(&g_sB, cudaStreamNonBlocking);
        cudaEventCreateWithFlags(&g_e0, cudaEventDisableTiming);
        cudaEventCreateWithFlags(&g_eX, cudaEventDisableTiming);
        cudaEventCreateWithFlags(&g_eW, cudaEventDisableTiming);
        cudaEventCreateWithFlags(&g_eV, cudaEventDisableTiming);
    }
} g_stream_init;

// ---------------------------------------------------------------------------
// helpers
// ---------------------------------------------------------------------------
__device__ __forceinline__ uint32_t smem_u32(const void* p) {
    uint32_t a;
    asm("{ .reg .u64 t; cvta.to.shared.u64 t, %1; cvt.u32.u64 %0, t; }"
        : "=r"(a) : "l"(p));
    return a;
}
__device__ __forceinline__ uint64_t gptr64(const void* p) {
    uint64_t g;
    asm("cvta.to.global.u64 %0, %1;" : "=l"(g) : "l"(p));
    return g;
}
__device__ __forceinline__ void cp16(uint32_t saddr, const void* g) {
    asm volatile("cp.async.cg.shared.global [%0], [%1], 16;"
                 :: "r"(saddr), "l"(gptr64(g)) : "memory");
}

// warp-level fp16 MMA, fp32 accumulate (fallback HMMA on sm_103)
__device__ __forceinline__ void mma16816(float* c, const uint32_t* a, const uint32_t* b) {
    asm volatile(
        "mma.sync.aligned.m16n8k16.row.col.f32.f16.f16.f32 "
        "{%0,%1,%2,%3}, {%4,%5,%6,%7}, {%8,%9}, {%0,%1,%2,%3};"
        : "+f"(c[0]), "+f"(c[1]), "+f"(c[2]), "+f"(c[3])
        : "r"(a[0]), "r"(a[1]), "r"(a[2]), "r"(a[3]), "r"(b[0]), "r"(b[1]));
}
__device__ __forceinline__ void ldm_x4(uint32_t* r, uint32_t addr) {
    asm volatile("ldmatrix.sync.aligned.m8n8.x4.shared.b16 {%0,%1,%2,%3}, [%4];"
                 : "=r"(r[0]), "=r"(r[1]), "=r"(r[2]), "=r"(r[3]) : "r"(addr));
}
// NON-transposed x2: correct for B stored [N,K] row-major (K-contiguous)
__device__ __forceinline__ void ldm_x2(uint32_t* r, uint32_t addr) {
    asm volatile("ldmatrix.sync.aligned.m8n8.x2.shared.b16 {%0,%1}, [%2];"
                 : "=r"(r[0]), "=r"(r[1]) : "r"(addr));
}

__device__ __forceinline__ void split1(float v, __half& h, __half& l) {
    h = __float2half(v);
    l = __float2half(v - __half2float(h));
}
__device__ __forceinline__ uint32_t pack2(__half a, __half b) {
    __half2 t; t.x = a; t.y = b;
    return *reinterpret_cast<uint32_t*>(&t);
}

// smem geometry: rows padded to 40 fp16 (80B) -> conflict-free ldmatrix
#define KC          32
#define ROW_PAD     40
#define A_TILE_BYTES (128 * ROW_PAD * 2)         // 10240
#define B_TILE_BYTES (256 * ROW_PAD * 2)         // 20480
#define OFF_AL      A_TILE_BYTES
#define OFF_BH      (2 * A_TILE_BYTES)
#define OFF_BL      (2 * A_TILE_BYTES + B_TILE_BYTES)
#define STAGE_BYTES (2 * A_TILE_BYTES + 2 * B_TILE_BYTES)  // 61440
#define N_STAGES    3
#define SMEM_BYTES  (N_STAGES * STAGE_BYTES)     // 184320

// ---------------------------------------------------------------------------
// NT GEMM: C = (Ah+Al)[M,K] @ (Bh+Bl)[N,K]^T, fp16 split.  (R8/R10 core)
// NPROD=3: hh+lh+hl. NPROD=2: hh+lh. NPROD=1: hh only.
// OM=0: fp32 C. OM=1: fp16 hi/lo split. OM=2: fp16 hi only.
// BMODE=0: none. BMODE=1: column bias. BMODE=2: row bias.
// CTA 128x256, 8 warps, warp tile 64x64, 3-stage cp.async pipeline.
// ---------------------------------------------------------------------------
template <int NPROD, int OM, int BMODE, bool RELU>
__global__ __launch_bounds__(256, 1)
void gemm_mma(const __half* __restrict__ Ah, const __half* __restrict__ Al,
              const __half* __restrict__ Bh, const __half* __restrict__ Bl,
              const float* __restrict__ bias, float* __restrict__ C,
              __half* __restrict__ Ch, __half* __restrict__ Cl,
              int Nn, int Kd, long long sA, long long sB, long long sC)
{
    extern __shared__ __align__(128) char smem[];
    const int tid = threadIdx.x;
    const long long z = blockIdx.z;
    Ah += z * sA;
    if (NPROD >= 2) Al += z * sA;
    Bh += z * sB;
    if (NPROD == 3) Bl += z * sB;
    const int row0 = blockIdx.y * 128;
    const int col0 = blockIdx.x * 256;

    const int warp  = tid >> 5;
    const int lane  = tid & 31;
    const int g     = lane >> 2;
    const int t     = lane & 3;
    const int mbase = (warp & 1) * 64;
    const int nbase = (warp >> 1) * 64;

    const uint32_t sbase = smem_u32(smem);

    const uint32_t a_off = (uint32_t)(((mbase + (lane & 15)) * ROW_PAD + (lane >> 4) * 8) * 2);
    const uint32_t b_off = (uint32_t)(((nbase + (lane & 7)) * ROW_PAD + ((lane >> 3) & 1) * 8) * 2);

    float acc[4][8][4];
#pragma unroll
    for (int mi = 0; mi < 4; mi++)
#pragma unroll
        for (int ni = 0; ni < 8; ni++)
#pragma unroll
            for (int r = 0; r < 4; r++) acc[mi][ni][r] = 0.f;

    auto load_stage = [&](int st, int kc) {
        const uint32_t sb = sbase + (uint32_t)st * STAGE_BYTES;
        const int k0 = kc * KC;
#pragma unroll
        for (int i = 0; i < 2; i++) {
            const int idx = tid + (i << 8);
            const int r  = idx >> 2;
            const int c4 = idx & 3;
            const uint32_t soff = (uint32_t)(r * 80 + c4 * 16);
            const long long ga = (long long)(row0 + r) * Kd + k0 + c4 * 8;
            cp16(sb + soff, Ah + ga);
            if (NPROD >= 2) cp16(sb + OFF_AL + soff, Al + ga);
        }
#pragma unroll
        for (int i = 0; i < 4; i++) {
            const int idx = tid + (i << 8);
            const int r  = idx >> 2;
            const int c4 = idx & 3;
            const uint32_t soff = (uint32_t)(r * 80 + c4 * 16);
            const long long gb = (long long)(col0 + r) * Kd + k0 + c4 * 8;
            cp16(sb + OFF_BH + soff, Bh + gb);
            if (NPROD == 3) cp16(sb + OFF_BL + soff, Bl + gb);
        }
        asm volatile("cp.async.commit_group;" ::: "memory");
    };

    auto compute_stage = [&](int st) {
        const uint32_t sb  = sbase + (uint32_t)st * STAGE_BYTES;
        const uint32_t aoh = sb + a_off;
        const uint32_t aol = aoh + OFF_AL;
        const uint32_t boh = sb + OFF_BH + b_off;
        const uint32_t bol = boh + B_TILE_BYTES;
#pragma unroll
        for (int kk = 0; kk < 2; kk++) {
            uint32_t ahf[4][4], bhf[8][2];
#pragma unroll
            for (int mi = 0; mi < 4; mi++) ldm_x4(ahf[mi], aoh + mi * 1280 + kk * 32);
#pragma unroll
            for (int ni = 0; ni < 8; ni++) ldm_x2(bhf[ni], boh + ni * 640 + kk * 32);
#pragma unroll
            for (int mi = 0; mi < 4; mi++)
#pragma unroll
                for (int ni = 0; ni < 8; ni++) mma16816(acc[mi][ni], ahf[mi], bhf[ni]);
            if (NPROD >= 2) {
                uint32_t alf[4][4];
#pragma unroll
                for (int mi = 0; mi < 4; mi++) ldm_x4(alf[mi], aol + mi * 1280 + kk * 32);
#pragma unroll
                for (int mi = 0; mi < 4; mi++)
#pragma unroll
                    for (int ni = 0; ni < 8; ni++) mma16816(acc[mi][ni], alf[mi], bhf[ni]);
            }
            if (NPROD == 3) {
                uint32_t blf[8][2];
#pragma unroll
                for (int ni = 0; ni < 8; ni++) ldm_x2(blf[ni], bol + ni * 640 + kk * 32);
#pragma unroll
                for (int mi = 0; mi < 4; mi++)
#pragma unroll
                    for (int ni = 0; ni < 8; ni++) mma16816(acc[mi][ni], ahf[mi], blf[ni]);
            }
        }
    };

    const int nc = Kd / KC;
    load_stage(0, 0);
    load_stage(1, 1);

    for (int c = 0; c < nc; c++) {
        if (c + 2 < nc) asm volatile("cp.async.wait_group 1;" ::: "memory");
        else            asm volatile("cp.async.wait_group 0;" ::: "memory");
        __syncthreads();
        compute_stage(c % N_STAGES);
        if (c + 2 < nc) load_stage((c + 2) % N_STAGES, c + 2);
    }

    // ---- epilogue ----
#pragma unroll
    for (int mi = 0; mi < 4; mi++) {
        const long long r = row0 + mbase + mi * 16 + g;
        float rb0 = 0.f, rb1 = 0.f;
        if (BMODE == 2) { rb0 = bias[r]; rb1 = bias[r + 8]; }
#pragma unroll
        for (int ni = 0; ni < 8; ni++) {
            const int cc = col0 + nbase + ni * 8 + t * 2;
            float2 v0, v1;
            v0.x = acc[mi][ni][0]; v0.y = acc[mi][ni][1];
            v1.x = acc[mi][ni][2]; v1.y = acc[mi][ni][3];
            if (BMODE == 1) {
                const float2 bv = *(const float2*)(bias + cc);
                v0.x += bv.x; v0.y += bv.y;
                v1.x += bv.x; v1.y += bv.y;
            } else if (BMODE == 2) {
                v0.x += rb0; v0.y += rb0;
                v1.x += rb1; v1.y += rb1;
            }
            if (RELU) {
                v0.x = fmaxf(v0.x, 0.f); v0.y = fmaxf(v0.y, 0.f);
                v1.x = fmaxf(v1.x, 0.f); v1.y = fmaxf(v1.y, 0.f);
            }
            if (OM == 0) {
                float* Cz = C + z * sC;
                *(float2*)(Cz + r * Nn + cc)       = v0;
                *(float2*)(Cz + (r + 8) * Nn + cc) = v1;
            } else if (OM == 1) {
                __half* Chz = Ch + z * sC;
                __half* Clz = Cl + z * sC;
                __half h0, h1, l0, l1;
                split1(v0.x, h0, l0); split1(v0.y, h1, l1);
                *(uint32_t*)(Chz + r * Nn + cc) = pack2(h0, h1);
                *(uint32_t*)(Clz + r * Nn + cc) = pack2(l0, l1);
                split1(v1.x, h0, l0); split1(v1.y, h1, l1);
                *(uint32_t*)(Chz + (r + 8) * Nn + cc) = pack2(h0, h1);
                *(uint32_t*)(Clz + (r + 8) * Nn + cc) = pack2(l0, l1);
            } else {
                __half* Chz = Ch + z * sC;
                *(uint32_t*)(Chz + r * Nn + cc) =
                    pack2(__float2half(v0.x), __float2half(v0.y));
                *(uint32_t*)(Chz + (r + 8) * Nn + cc) =
                    pack2(__float2half(v1.x), __float2half(v1.y));
            }
        }
    }
}

// ---------------------------------------------------------------------------
// fp32 -> fp16 hi/lo elementwise split
// ---------------------------------------------------------------------------
__global__ __launch_bounds__(256)
void split_kernel(const float* __restrict__ in, __half* __restrict__ oh,
                  __half* __restrict__ ol, long long n4)
{
    long long i = (long long)blockIdx.x * blockDim.x + threadIdx.x;
    if (i >= n4) return;
    float4 v = ((const float4*)in)[i];
    __half h0, h1, h2, h3, l0, l1, l2, l3;
    split1(v.x, h0, l0); split1(v.y, h1, l1);
    split1(v.z, h2, l2); split1(v.w, h3, l3);
    uint2 hv, lv;
    hv.x = pack2(h0, h1); hv.y = pack2(h2, h3);
    lv.x = pack2(l0, l1); lv.y = pack2(l2, l3);
    ((uint2*)oh)[i] = hv;
    ((uint2*)ol)[i] = lv;
}

// ---------------------------------------------------------------------------
// fp32 -> fp16 hi only
// ---------------------------------------------------------------------------
__global__ __launch_bounds__(256)
void split_hi_kernel(const float* __restrict__ in, __half* __restrict__ oh,
                     long long n4)
{
    long long i = (long long)blockIdx.x * blockDim.x + threadIdx.x;
    if (i >= n4) return;
    float4 v = ((const float4*)in)[i];
    uint2 hv;
    hv.x = pack2(__float2half(v.x), __float2half(v.y));
    hv.y = pack2(__float2half(v.z), __float2half(v.w));
    ((uint2*)oh)[i] = hv;
}

// ---------------------------------------------------------------------------
// fp32 [R,C] -> transposed fp16 hi/lo [C,R] (batched via blockIdx.z)
// ---------------------------------------------------------------------------
__global__ __launch_bounds__(256)
void tsplit_kernel(const float* __restrict__ in, __half* __restrict__ oh,
                   __half* __restrict__ ol, int R, int C)
{
    __shared__ float t[32][33];
    const long long zoff = (long long)blockIdx.z * R * C;
    in += zoff; oh += zoff; ol += zoff;
    const int tx = threadIdx.x, ty = threadIdx.y;
    const int x = blockIdx.x * 32 + tx;
    const int y0 = blockIdx.y * 32 + ty;
#pragma unroll
    for (int i = 0; i < 32; i += 8)
        t[ty + i][tx] = in[(long long)(y0 + i) * C + x];
    __syncthreads();
    const int ox = blockIdx.y * 32 + tx;
    const int oy0 = blockIdx.x * 32 + ty;
#pragma unroll
    for (int i = 0; i < 32; i += 8) {
        float v = t[tx][ty + i];
        __half h, l;
        split1(v, h, l);
        oh[(long long)(oy0 + i) * R + ox] = h;
        ol[(long long)(oy0 + i) * R + ox] = l;
    }
}

// ---------------------------------------------------------------------------
// warp-per-row matvec: out[r] = sum_c Mrow[r,:]*v[:]   (C = D_EMB)
// ---------------------------------------------------------------------------
__inline__ __device__ float warpSum(float v) {
#pragma unroll
    for (int o = 16; o > 0; o >>= 1) v += __shfl_xor_sync(0xffffffffu, v, o);
    return v;
}
__inline__ __device__ float warpMax(float v) {
#pragma unroll
    for (int o = 16; o > 0; o >>= 1) v = fmaxf(v, __shfl_xor_sync(0xffffffffu, v, o));
    return v;
}

__global__ __launch_bounds__(256)
void matvec_kernel(const float* __restrict__ Mrow, const float* __restrict__ v,
                   float* __restrict__ out)
{
    const int row  = blockIdx.x * 8 + (threadIdx.x >> 5);
    const int lane = threadIdx.x & 31;
    const float* R = Mrow + (long long)row * D_EMB;
    float s = 0.f;
#pragma unroll
    for (int d = lane * 4; d < D_EMB; d += 128) {
        const float4 a = *(const float4*)(R + d);
        const float4 b = *(const float4*)(v + d);
        s += a.x * b.x + a.y * b.y + a.z * b.z + a.w * b.w;
    }
    s = warpSum(s);
    if (lane == 0) out[row] = s;
}

// ---------------------------------------------------------------------------
// Row softmax over 2048 fp32 (+ per-i offset w) -> fp16 hi output only
// ---------------------------------------------------------------------------
__global__ __launch_bounds__(256)
void softmax_split(const float* __restrict__ S, const float* __restrict__ w,
                   __half* __restrict__ ah)
{
    const long long base = (long long)blockIdx.x * N_SEQ;
    const float* row = S + base;
    const float* wb  = w + (long long)(blockIdx.x >> 11) * N_SEQ;
    const int tid = threadIdx.x;
    const int lane = tid & 31;
    const int wid = tid >> 5;

    float4 v0 = ((const float4*)row)[tid];
    float4 v1 = ((const float4*)row)[tid + 256];
    const float4 w0 = ((const float4*)wb)[tid];
    const float4 w1 = ((const float4*)wb)[tid + 256];
    v0.x += w0.x; v0.y += w0.y; v0.z += w0.z; v0.w += w0.w;
    v1.x += w1.x; v1.y += w1.y; v1.z += w1.z; v1.w += w1.w;

    __shared__ float sm[8];
    float m = fmaxf(fmaxf(fmaxf(v0.x, v0.y), fmaxf(v0.z, v0.w)),
                    fmaxf(fmaxf(v1.x, v1.y), fmaxf(v1.z, v1.w)));
    m = warpMax(m);
    if (lane == 0) sm[wid] = m;
    __syncthreads();
    if (wid == 0) {
        float t = (lane < 8) ? sm[lane] : -3.402823e38f;
        t = warpMax(t);
        if (lane == 0) sm[0] = t;
    }
    __syncthreads();
    m = sm[0];
    __syncthreads();

    v0.x = expf(v0.x - m); v0.y = expf(v0.y - m);
    v0.z = expf(v0.z - m); v0.w = expf(v0.w - m);
    v1.x = expf(v1.x - m); v1.y = expf(v1.y - m);
    v1.z = expf(v1.z - m); v1.w = expf(v1.w - m);

    float s = (v0.x + v0.y + v0.z + v0.w) + (v1.x + v1.y + v1.z + v1.w);
    s = warpSum(s);
    if (lane == 0) sm[wid] = s;
    __syncthreads();
    if (wid == 0) {
        float t = (lane < 8) ? sm[lane] : 0.f;
        t = warpSum(t);
        if (lane == 0) sm[0] = t;
    }
    __syncthreads();
    const float inv = 1.0f / sm[0];

    uint2 hv;
    hv.x = pack2(__float2half(v0.x * inv), __float2half(v0.y * inv));
    hv.y = pack2(__float2half(v0.z * inv), __float2half(v0.w * inv));
    ((uint2*)(ah + base))[tid] = hv;
    hv.x = pack2(__float2half(v1.x * inv), __float2half(v1.y * inv));
    hv.y = pack2(__float2half(v1.z * inv), __float2half(v1.w * inv));
    ((uint2*)(ah + base))[tid + 256] = hv;
}

// ---------------------------------------------------------------------------
extern "C" void kernel_launch(void* const* d_in, const int* in_sizes, int n_in,
                              void* d_out, int out_size)
{
    const float* x  = (const float*)d_in[0];
    const float* Wq = (const float*)d_in[1];
    const float* bq = (const float*)d_in[2];
    const float* Wk = (const float*)d_in[3];
    const float* bk = (const float*)d_in[4];
    const float* Wv = (const float*)d_in[5];
    const float* bv = (const float*)d_in[6];
    const float* Wm = (const float*)d_in[7];
    const float* bm = (const float*)d_in[8];
    float* out = (float*)d_out;
    (void)bq;  // bq enters scores only via terms constant along the softmax axis

    __half *xh, *xl, *Wqh, *Wql, *Wkh, *Wkl, *Wvh, *Wvl, *Wmh, *Wml;
    __half *M2h, *M2l, *Zh, *Zl, *Vh, *VWt, *ah;
    float *Vf, *S, *wv, *w;
    cudaGetSymbolAddress((void**)&xh, g_xh);   cudaGetSymbolAddress((void**)&xl, g_xl);
    cudaGetSymbolAddress((void**)&Wqh, g_Wqh); cudaGetSymbolAddress((void**)&Wql, g_Wql);
    cudaGetSymbolAddress((void**)&Wkh, g_Wkh); cudaGetSymbolAddress((void**)&Wkl, g_Wkl);
    cudaGetSymbolAddress((void**)&Wvh, g_Wvh); cudaGetSymbolAddress((void**)&Wvl, g_Wvl);
    cudaGetSymbolAddress((void**)&Wmh, g_Wmh); cudaGetSymbolAddress((void**)&Wml, g_Wml);
    cudaGetSymbolAddress((void**)&M2h, g_M2h); cudaGetSymbolAddress((void**)&M2l, g_M2l);
    cudaGetSymbolAddress((void**)&Zh, g_Zh);   cudaGetSymbolAddress((void**)&Zl, g_Zl);
    cudaGetSymbolAddress((void**)&Vf, g_Vf);
    cudaGetSymbolAddress((void**)&Vh, g_Vh);
    cudaGetSymbolAddress((void**)&VWt, g_VWt);
    cudaGetSymbolAddress((void**)&ah, g_ah);
    cudaGetSymbolAddress((void**)&S, g_S);
    cudaGetSymbolAddress((void**)&wv, g_wv);   cudaGetSymbolAddress((void**)&w, g_w);

    cudaFuncSetAttribute(gemm_mma<3, 1, 0, false>,
                         cudaFuncAttributeMaxDynamicSharedMemorySize, SMEM_BYTES);
    cudaFuncSetAttribute(gemm_mma<3, 0, 0, false>,
                         cudaFuncAttributeMaxDynamicSharedMemorySize, SMEM_BYTES);
    cudaFuncSetAttribute(gemm_mma<1, 0, 1, false>,
                         cudaFuncAttributeMaxDynamicSharedMemorySize, SMEM_BYTES);
    cudaFuncSetAttribute(gemm_mma<1, 2, 0, false>,
                         cudaFuncAttributeMaxDynamicSharedMemorySize, SMEM_BYTES);
    cudaFuncSetAttribute(gemm_mma<1, 0, 1, true>,
                         cudaFuncAttributeMaxDynamicSharedMemorySize, SMEM_BYTES);

    const long long nX = (long long)BN_TOT * D_EMB;
    const long long nW = (long long)D_EMB * D_EMB;

    // ---- fork side stream (exact R10 topology) ----
    cudaEventRecord(g_e0, 0);
    cudaStreamWaitEvent(g_sB, g_e0, 0);

    // side stream: weight transposes + bias matvecs
    {
        dim3 g(D_EMB / 32, D_EMB / 32, 1), b(32, 8);
        tsplit_kernel<<<g, b, 0, g_sB>>>(Wv, Wvh, Wvl, D_EMB, D_EMB);
        tsplit_kernel<<<g, b, 0, g_sB>>>(Wm, Wmh, Wml, D_EMB, D_EMB);
    }
    matvec_kernel<<<D_EMB / 8, 256, 0, g_sB>>>(Wq, bk, wv);
    matvec_kernel<<<BN_TOT / 8, 256, 0, g_sB>>>(x, wv, w);
    cudaEventRecord(g_eW, g_sB);

    // main stream: split x
    split_kernel<<<(unsigned)((nX / 4 + 255) / 256), 256>>>(x, xh, xl, nX / 4);
    cudaEventRecord(g_eX, 0);
    cudaStreamWaitEvent(g_sB, g_eX, 0);

    // side stream (R10 slot): V projection (1-MMA) -> fp32 Vf (with bv),
    // then plain hi split, then VWt[e,i] = sum_d Wm^T[e,d] * V[i,d]  (1-MMA)
    {
        dim3 g(D_EMB / 256, BN_TOT / 128, 1);
        gemm_mma<1, 0, 1, false><<<g, 256, SMEM_BYTES, g_sB>>>(
            xh, nullptr, Wvh, nullptr, bv, Vf, nullptr, nullptr,
            D_EMB, D_EMB, 0, 0, 0);
    }
    split_hi_kernel<<<(unsigned)((nX / 4 + 255) / 256), 256, 0, g_sB>>>(Vf, Vh, nX / 4);
    {
        // A = Wmh [e,d] (shared across batches), B = Vh_b [i,d]; C = VWt_b [e,i]
        dim3 g(N_SEQ / 256, D_EMB / 128, N_BATCH);
        gemm_mma<1, 2, 0, false><<<g, 256, SMEM_BYTES, g_sB>>>(
            Wmh, nullptr, Vh, nullptr, nullptr, nullptr, VWt, nullptr,
            N_SEQ, D_EMB, 0, (long long)N_SEQ * D_EMB,
            (long long)D_EMB * N_SEQ);
    }
    cudaEventRecord(g_eV, g_sB);

    // main stream: Wq/Wk splits -> M2 (monolithic) -> Z
    split_kernel<<<(unsigned)((nW / 4 + 255) / 256), 256>>>(Wq, Wqh, Wql, nW / 4);
    split_kernel<<<(unsigned)((nW / 4 + 255) / 256), 256>>>(Wk, Wkh, Wkl, nW / 4);
    {
        dim3 g(D_EMB / 256, D_EMB / 128, 1);
        gemm_mma<3, 1, 0, false><<<g, 256, SMEM_BYTES>>>(
            Wqh, Wql, Wkh, Wkl, nullptr, nullptr, M2h, M2l, D_EMB, D_EMB, 0, 0, 0);
    }
    {
        dim3 g(D_EMB / 256, BN_TOT / 128, 1);
        gemm_mma<3, 1, 0, false><<<g, 256, SMEM_BYTES>>>(
            xh, xl, M2h, M2l, nullptr, nullptr, Zh, Zl, D_EMB, D_EMB, 0, 0, 0);
    }

    // main stream: S (single batched launch)
    {
        dim3 g(N_SEQ / 256, N_SEQ / 128, N_BATCH);
        gemm_mma<3, 0, 0, false><<<g, 256, SMEM_BYTES>>>(
            Zh, Zl, xh, xl, nullptr, S, nullptr, nullptr,
            N_SEQ, D_EMB,
            (long long)N_SEQ * D_EMB, (long long)N_SEQ * D_EMB,
            (long long)N_SEQ * N_SEQ);
    }

    // softmax (needs w), then single fused tail GEMM:
    // out[j,e] = relu( sum_i alpha[j,i] * VWt[e,i] + bm[e] )
    cudaStreamWaitEvent(0, g_eW, 0);
    softmax_split<<<BN_TOT, 256>>>(S, w, ah);

    cudaStreamWaitEvent(0, g_eV, 0);
    {
        dim3 g(D_EMB / 256, N_SEQ / 128, N_BATCH);
        gemm_mma<1, 0, 1, true><<<g, 256, SMEM_BYTES>>>(
            ah, nullptr, VWt, nullptr, bm, out, nullptr, nullptr,
            D_EMB, N_SEQ,
            (long long)N_SEQ * N_SEQ, (long long)D_EMB * N_SEQ,
            (long long)N_SEQ * D_EMB);
    }
}

// round 17
// speedup vs baseline: 1.1594x; 1.0027x over previous
#include <cuda_runtime.h>
#include <cuda_fp16.h>
#include <stdint.h>
#include <math.h>

#define D_EMB   1024
#define N_BATCH 4
#define N_SEQ   2048
#define BN_TOT  (N_BATCH * N_SEQ)   // 8192

// ---------------------------------------------------------------------------
// Device scratch (allocation-free per harness rules)
// ---------------------------------------------------------------------------
__device__ __half g_xh[BN_TOT * D_EMB], g_xl[BN_TOT * D_EMB];
__device__ __half g_Wqh[D_EMB * D_EMB], g_Wql[D_EMB * D_EMB];  // plain split
__device__ __half g_Wkh[D_EMB * D_EMB], g_Wkl[D_EMB * D_EMB];  // plain split
__device__ __half g_Wvh[D_EMB * D_EMB], g_Wvl[D_EMB * D_EMB];  // transposed split
__device__ __half g_Wmh[D_EMB * D_EMB], g_Wml[D_EMB * D_EMB];  // transposed split
__device__ __half g_M2h[D_EMB * D_EMB], g_M2l[D_EMB * D_EMB];  // Wq*Wk^T
__device__ __half g_Zh[BN_TOT * D_EMB], g_Zl[BN_TOT * D_EMB];  // x*M
__device__ float g_Vf[BN_TOT * D_EMB];
__device__ __half g_Vh[BN_TOT * D_EMB];                        // V hi, [i,d] plain
__device__ __half g_VWt[(size_t)N_BATCH * D_EMB * N_SEQ];      // (V@Wm)^T hi, [e,i]
__device__ float g_S[(size_t)N_BATCH * N_SEQ * N_SEQ];
__device__ __half g_ah[(size_t)N_BATCH * N_SEQ * N_SEQ];   // alpha hi only
__device__ float g_wv[D_EMB];     // Wq * bk
__device__ float g_w[BN_TOT];     // x * (Wq*bk)

// ---------------------------------------------------------------------------
// static streams/events
// ---------------------------------------------------------------------------
static cudaStream_t g_sB;
static cudaEvent_t g_e0, g_eX, g_eW, g_eV;
static struct StreamInit {
    StreamInit() {
        cudaStreamCreateWithFlags(&g_sB, cudaStreamNonBlocking);
        cudaEventCreateWithFlags(&g_e0, cudaEventDisableTiming);
        cudaEventCreateWithFlags(&g_eX, cudaEventDisableTiming);
        cudaEventCreateWithFlags(&g_eW, cudaEventDisableTiming);
        cudaEventCreateWithFlags(&g_eV, cudaEventDisableTiming);
    }
} g_stream_init;

// ---------------------------------------------------------------------------
// helpers
// ---------------------------------------------------------------------------
__device__ __forceinline__ uint32_t smem_u32(const void* p) {
    uint32_t a;
    asm("{ .reg .u64 t; cvta.to.shared.u64 t, %1; cvt.u32.u64 %0, t; }"
        : "=r"(a) : "l"(p));
    return a;
}
__device__ __forceinline__ uint64_t gptr64(const void* p) {
    uint64_t g;
    asm("cvta.to.global.u64 %0, %1;" : "=l"(g) : "l"(p));
    return g;
}
__device__ __forceinline__ void cp16(uint32_t saddr, const void* g) {
    asm volatile("cp.async.cg.shared.global [%0], [%1], 16;"
                 :: "r"(saddr), "l"(gptr64(g)) : "memory");
}

// warp-level fp16 MMA, fp32 accumulate (fallback HMMA on sm_103)
__device__ __forceinline__ void mma16816(float* c, const uint32_t* a, const uint32_t* b) {
    asm volatile(
        "mma.sync.aligned.m16n8k16.row.col.f32.f16.f16.f32 "
        "{%0,%1,%2,%3}, {%4,%5,%6,%7}, {%8,%9}, {%0,%1,%2,%3};"
        : "+f"(c[0]), "+f"(c[1]), "+f"(c[2]), "+f"(c[3])
        : "r"(a[0]), "r"(a[1]), "r"(a[2]), "r"(a[3]), "r"(b[0]), "r"(b[1]));
}
__device__ __forceinline__ void ldm_x4(uint32_t* r, uint32_t addr) {
    asm volatile("ldmatrix.sync.aligned.m8n8.x4.shared.b16 {%0,%1,%2,%3}, [%4];"
                 : "=r"(r[0]), "=r"(r[1]), "=r"(r[2]), "=r"(r[3]) : "r"(addr));
}
// NON-transposed x2: correct for B stored [N,K] row-major (K-contiguous)
__device__ __forceinline__ void ldm_x2(uint32_t* r, uint32_t addr) {
    asm volatile("ldmatrix.sync.aligned.m8n8.x2.shared.b16 {%0,%1}, [%2];"
                 : "=r"(r[0]), "=r"(r[1]) : "r"(addr));
}

__device__ __forceinline__ void split1(float v, __half& h, __half& l) {
    h = __float2half(v);
    l = __float2half(v - __half2float(h));
}
__device__ __forceinline__ uint32_t pack2(__half a, __half b) {
    __half2 t; t.x = a; t.y = b;
    return *reinterpret_cast<uint32_t*>(&t);
}

// smem geometry: rows padded to 40 fp16 (80B) -> conflict-free ldmatrix
#define KC          32
#define ROW_PAD     40
#define A_TILE_BYTES (128 * ROW_PAD * 2)         // 10240
#define B_TILE_BYTES (256 * ROW_PAD * 2)         // 20480
#define OFF_AL      A_TILE_BYTES
#define OFF_BH      (2 * A_TILE_BYTES)
#define OFF_BL      (2 * A_TILE_BYTES + B_TILE_BYTES)
#define STAGE_BYTES (2 * A_TILE_BYTES + 2 * B_TILE_BYTES)  // 61440
#define N_STAGES    3
#define SMEM_BYTES  (N_STAGES * STAGE_BYTES)     // 184320

// ---------------------------------------------------------------------------
// NT GEMM: C = (Ah+Al)[M,K] @ (Bh+Bl)[N,K]^T, fp16 split.  (R8/R10 core)
// NPROD=3: hh+lh+hl. NPROD=2: hh+lh. NPROD=1: hh only.
// OM=0: fp32 C. OM=1: fp16 hi/lo split. OM=2: fp16 hi only.
// BMODE=0: none. BMODE=1: column bias. BMODE=2: row bias.
// CTA 128x256, 8 warps, warp tile 64x64, 3-stage cp.async pipeline.
// ---------------------------------------------------------------------------
template <int NPROD, int OM, int BMODE, bool RELU>
__global__ __launch_bounds__(256, 1)
void gemm_mma(const __half* __restrict__ Ah, const __half* __restrict__ Al,
              const __half* __restrict__ Bh, const __half* __restrict__ Bl,
              const float* __restrict__ bias, float* __restrict__ C,
              __half* __restrict__ Ch, __half* __restrict__ Cl,
              int Nn, int Kd, long long sA, long long sB, long long sC)
{
    extern __shared__ __align__(128) char smem[];
    const int tid = threadIdx.x;
    const long long z = blockIdx.z;
    Ah += z * sA;
    if (NPROD >= 2) Al += z * sA;
    Bh += z * sB;
    if (NPROD == 3) Bl += z * sB;
    const int row0 = blockIdx.y * 128;
    const int col0 = blockIdx.x * 256;

    const int warp  = tid >> 5;
    const int lane  = tid & 31;
    const int g     = lane >> 2;
    const int t     = lane & 3;
    const int mbase = (warp & 1) * 64;
    const int nbase = (warp >> 1) * 64;

    const uint32_t sbase = smem_u32(smem);

    const uint32_t a_off = (uint32_t)(((mbase + (lane & 15)) * ROW_PAD + (lane >> 4) * 8) * 2);
    const uint32_t b_off = (uint32_t)(((nbase + (lane & 7)) * ROW_PAD + ((lane >> 3) & 1) * 8) * 2);

    float acc[4][8][4];
#pragma unroll
    for (int mi = 0; mi < 4; mi++)
#pragma unroll
        for (int ni = 0; ni < 8; ni++)
#pragma unroll
            for (int r = 0; r < 4; r++) acc[mi][ni][r] = 0.f;

    auto load_stage = [&](int st, int kc) {
        const uint32_t sb = sbase + (uint32_t)st * STAGE_BYTES;
        const int k0 = kc * KC;
#pragma unroll
        for (int i = 0; i < 2; i++) {
            const int idx = tid + (i << 8);
            const int r  = idx >> 2;
            const int c4 = idx & 3;
            const uint32_t soff = (uint32_t)(r * 80 + c4 * 16);
            const long long ga = (long long)(row0 + r) * Kd + k0 + c4 * 8;
            cp16(sb + soff, Ah + ga);
            if (NPROD >= 2) cp16(sb + OFF_AL + soff, Al + ga);
        }
#pragma unroll
        for (int i = 0; i < 4; i++) {
            const int idx = tid + (i << 8);
            const int r  = idx >> 2;
            const int c4 = idx & 3;
            const uint32_t soff = (uint32_t)(r * 80 + c4 * 16);
            const long long gb = (long long)(col0 + r) * Kd + k0 + c4 * 8;
            cp16(sb + OFF_BH + soff, Bh + gb);
            if (NPROD == 3) cp16(sb + OFF_BL + soff, Bl + gb);
        }
        asm volatile("cp.async.commit_group;" ::: "memory");
    };

    auto compute_stage = [&](int st) {
        const uint32_t sb  = sbase + (uint32_t)st * STAGE_BYTES;
        const uint32_t aoh = sb + a_off;
        const uint32_t aol = aoh + OFF_AL;
        const uint32_t boh = sb + OFF_BH + b_off;
        const uint32_t bol = boh + B_TILE_BYTES;
#pragma unroll
        for (int kk = 0; kk < 2; kk++) {
            uint32_t ahf[4][4], bhf[8][2];
#pragma unroll
            for (int mi = 0; mi < 4; mi++) ldm_x4(ahf[mi], aoh + mi * 1280 + kk * 32);
#pragma unroll
            for (int ni = 0; ni < 8; ni++) ldm_x2(bhf[ni], boh + ni * 640 + kk * 32);
#pragma unroll
            for (int mi = 0; mi < 4; mi++)
#pragma unroll
                for (int ni = 0; ni < 8; ni++) mma16816(acc[mi][ni], ahf[mi], bhf[ni]);
            if (NPROD >= 2) {
                uint32_t alf[4][4];
#pragma unroll
                for (int mi = 0; mi < 4; mi++) ldm_x4(alf[mi], aol + mi * 1280 + kk * 32);
#pragma unroll
                for (int mi = 0; mi < 4; mi++)
#pragma unroll
                    for (int ni = 0; ni < 8; ni++) mma16816(acc[mi][ni], alf[mi], bhf[ni]);
            }
            if (NPROD == 3) {
                uint32_t blf[8][2];
#pragma unroll
                for (int ni = 0; ni < 8; ni++) ldm_x2(blf[ni], bol + ni * 640 + kk * 32);
#pragma unroll
                for (int mi = 0; mi < 4; mi++)
#pragma unroll
                    for (int ni = 0; ni < 8; ni++) mma16816(acc[mi][ni], ahf[mi], blf[ni]);
            }
        }
    };

    const int nc = Kd / KC;
    load_stage(0, 0);
    load_stage(1, 1);

    for (int c = 0; c < nc; c++) {
        if (c + 2 < nc) asm volatile("cp.async.wait_group 1;" ::: "memory");
        else            asm volatile("cp.async.wait_group 0;" ::: "memory");
        __syncthreads();
        compute_stage(c % N_STAGES);
        if (c + 2 < nc) load_stage((c + 2) % N_STAGES, c + 2);
    }

    // ---- epilogue ----
#pragma unroll
    for (int mi = 0; mi < 4; mi++) {
        const long long r = row0 + mbase + mi * 16 + g;
        float rb0 = 0.f, rb1 = 0.f;
        if (BMODE == 2) { rb0 = bias[r]; rb1 = bias[r + 8]; }
#pragma unroll
        for (int ni = 0; ni < 8; ni++) {
            const int cc = col0 + nbase + ni * 8 + t * 2;
            float2 v0, v1;
            v0.x = acc[mi][ni][0]; v0.y = acc[mi][ni][1];
            v1.x = acc[mi][ni][2]; v1.y = acc[mi][ni][3];
            if (BMODE == 1) {
                const float2 bv = *(const float2*)(bias + cc);
                v0.x += bv.x; v0.y += bv.y;
                v1.x += bv.x; v1.y += bv.y;
            } else if (BMODE == 2) {
                v0.x += rb0; v0.y += rb0;
                v1.x += rb1; v1.y += rb1;
            }
            if (RELU) {
                v0.x = fmaxf(v0.x, 0.f); v0.y = fmaxf(v0.y, 0.f);
                v1.x = fmaxf(v1.x, 0.f); v1.y = fmaxf(v1.y, 0.f);
            }
            if (OM == 0) {
                float* Cz = C + z * sC;
                *(float2*)(Cz + r * Nn + cc)       = v0;
                *(float2*)(Cz + (r + 8) * Nn + cc) = v1;
            } else if (OM == 1) {
                __half* Chz = Ch + z * sC;
                __half* Clz = Cl + z * sC;
                __half h0, h1, l0, l1;
                split1(v0.x, h0, l0); split1(v0.y, h1, l1);
                *(uint32_t*)(Chz + r * Nn + cc) = pack2(h0, h1);
                *(uint32_t*)(Clz + r * Nn + cc) = pack2(l0, l1);
                split1(v1.x, h0, l0); split1(v1.y, h1, l1);
                *(uint32_t*)(Chz + (r + 8) * Nn + cc) = pack2(h0, h1);
                *(uint32_t*)(Clz + (r + 8) * Nn + cc) = pack2(l0, l1);
            } else {
                __half* Chz = Ch + z * sC;
                *(uint32_t*)(Chz + r * Nn + cc) =
                    pack2(__float2half(v0.x), __float2half(v0.y));
                *(uint32_t*)(Chz + (r + 8) * Nn + cc) =
                    pack2(__float2half(v1.x), __float2half(v1.y));
            }
        }
    }
}

// ---------------------------------------------------------------------------
// fp32 -> fp16 hi/lo elementwise split
// ---------------------------------------------------------------------------
__global__ __launch_bounds__(256)
void split_kernel(const float* __restrict__ in, __half* __restrict__ oh,
                  __half* __restrict__ ol, long long n4)
{
    long long i = (long long)blockIdx.x * blockDim.x + threadIdx.x;
    if (i >= n4) return;
    float4 v = ((const float4*)in)[i];
    __half h0, h1, h2, h3, l0, l1, l2, l3;
    split1(v.x, h0, l0); split1(v.y, h1, l1);
    split1(v.z, h2, l2); split1(v.w, h3, l3);
    uint2 hv, lv;
    hv.x = pack2(h0, h1); hv.y = pack2(h2, h3);
    lv.x = pack2(l0, l1); lv.y = pack2(l2, l3);
    ((uint2*)oh)[i] = hv;
    ((uint2*)ol)[i] = lv;
}

// dual split: Wq and Wk in one launch (one weight each per half-grid)
__global__ __launch_bounds__(256)
void split2_kernel(const float* __restrict__ inA, __half* __restrict__ ohA,
                   __half* __restrict__ olA,
                   const float* __restrict__ inB, __half* __restrict__ ohB,
                   __half* __restrict__ olB, long long n4)
{
    long long i = (long long)blockIdx.x * blockDim.x + threadIdx.x;
    const float* in; __half *oh, *ol;
    if (i >= n4) {
        i -= n4;
        if (i >= n4) return;
        in = inB; oh = ohB; ol = olB;
    } else {
        in = inA; oh = ohA; ol = olA;
    }
    float4 v = ((const float4*)in)[i];
    __half h0, h1, h2, h3, l0, l1, l2, l3;
    split1(v.x, h0, l0); split1(v.y, h1, l1);
    split1(v.z, h2, l2); split1(v.w, h3, l3);
    uint2 hv, lv;
    hv.x = pack2(h0, h1); hv.y = pack2(h2, h3);
    lv.x = pack2(l0, l1); lv.y = pack2(l2, l3);
    ((uint2*)oh)[i] = hv;
    ((uint2*)ol)[i] = lv;
}

// fp32 -> fp16 hi only
__global__ __launch_bounds__(256)
void split_hi_kernel(const float* __restrict__ in, __half* __restrict__ oh,
                     long long n4)
{
    long long i = (long long)blockIdx.x * blockDim.x + threadIdx.x;
    if (i >= n4) return;
    float4 v = ((const float4*)in)[i];
    uint2 hv;
    hv.x = pack2(__float2half(v.x), __float2half(v.y));
    hv.y = pack2(__float2half(v.z), __float2half(v.w));
    ((uint2*)oh)[i] = hv;
}

// ---------------------------------------------------------------------------
// fp32 [R,C] -> transposed fp16 hi/lo [C,R] (batched via blockIdx.z)
// ---------------------------------------------------------------------------
__global__ __launch_bounds__(256)
void tsplit_kernel(const float* __restrict__ in, __half* __restrict__ oh,
                   __half* __restrict__ ol, int R, int C)
{
    __shared__ float t[32][33];
    const long long zoff = (long long)blockIdx.z * R * C;
    in += zoff; oh += zoff; ol += zoff;
    const int tx = threadIdx.x, ty = threadIdx.y;
    const int x = blockIdx.x * 32 + tx;
    const int y0 = blockIdx.y * 32 + ty;
#pragma unroll
    for (int i = 0; i < 32; i += 8)
        t[ty + i][tx] = in[(long long)(y0 + i) * C + x];
    __syncthreads();
    const int ox = blockIdx.y * 32 + tx;
    const int oy0 = blockIdx.x * 32 + ty;
#pragma unroll
    for (int i = 0; i < 32; i += 8) {
        float v = t[tx][ty + i];
        __half h, l;
        split1(v, h, l);
        oh[(long long)(oy0 + i) * R + ox] = h;
        ol[(long long)(oy0 + i) * R + ox] = l;
    }
}

// ---------------------------------------------------------------------------
// warp-per-row matvec: out[r] = sum_c Mrow[r,:]*v[:]   (C = D_EMB)
// ---------------------------------------------------------------------------
__inline__ __device__ float warpSum(float v) {
#pragma unroll
    for (int o = 16; o > 0; o >>= 1) v += __shfl_xor_sync(0xffffffffu, v, o);
    return v;
}
__inline__ __device__ float warpMax(float v) {
#pragma unroll
    for (int o = 16; o > 0; o >>= 1) v = fmaxf(v, __shfl_xor_sync(0xffffffffu, v, o));
    return v;
}

__global__ __launch_bounds__(256)
void matvec_kernel(const float* __restrict__ Mrow, const float* __restrict__ v,
                   float* __restrict__ out)
{
    const int row  = blockIdx.x * 8 + (threadIdx.x >> 5);
    const int lane = threadIdx.x & 31;
    const float* R = Mrow + (long long)row * D_EMB;
    float s = 0.f;
#pragma unroll
    for (int d = lane * 4; d < D_EMB; d += 128) {
        const float4 a = *(const float4*)(R + d);
        const float4 b = *(const float4*)(v + d);
        s += a.x * b.x + a.y * b.y + a.z * b.z + a.w * b.w;
    }
    s = warpSum(s);
    if (lane == 0) out[row] = s;
}

// ---------------------------------------------------------------------------
// Row softmax over 2048 fp32 (+ per-i offset w) -> fp16 hi output only
// ---------------------------------------------------------------------------
__global__ __launch_bounds__(256)
void softmax_split(const float* __restrict__ S, const float* __restrict__ w,
                   __half* __restrict__ ah)
{
    const long long base = (long long)blockIdx.x * N_SEQ;
    const float* row = S + base;
    const float* wb  = w + (long long)(blockIdx.x >> 11) * N_SEQ;
    const int tid = threadIdx.x;
    const int lane = tid & 31;
    const int wid = tid >> 5;

    float4 v0 = ((const float4*)row)[tid];
    float4 v1 = ((const float4*)row)[tid + 256];
    const float4 w0 = ((const float4*)wb)[tid];
    const float4 w1 = ((const float4*)wb)[tid + 256];
    v0.x += w0.x; v0.y += w0.y; v0.z += w0.z; v0.w += w0.w;
    v1.x += w1.x; v1.y += w1.y; v1.z += w1.z; v1.w += w1.w;

    __shared__ float sm[8];
    float m = fmaxf(fmaxf(fmaxf(v0.x, v0.y), fmaxf(v0.z, v0.w)),
                    fmaxf(fmaxf(v1.x, v1.y), fmaxf(v1.z, v1.w)));
    m = warpMax(m);
    if (lane == 0) sm[wid] = m;
    __syncthreads();
    if (wid == 0) {
        float t = (lane < 8) ? sm[lane] : -3.402823e38f;
        t = warpMax(t);
        if (lane == 0) sm[0] = t;
    }
    __syncthreads();
    m = sm[0];
    __syncthreads();

    v0.x = expf(v0.x - m); v0.y = expf(v0.y - m);
    v0.z = expf(v0.z - m); v0.w = expf(v0.w - m);
    v1.x = expf(v1.x - m); v1.y = expf(v1.y - m);
    v1.z = expf(v1.z - m); v1.w = expf(v1.w - m);

    float s = (v0.x + v0.y + v0.z + v0.w) + (v1.x + v1.y + v1.z + v1.w);
    s = warpSum(s);
    if (lane == 0) sm[wid] = s;
    __syncthreads();
    if (wid == 0) {
        float t = (lane < 8) ? sm[lane] : 0.f;
        t = warpSum(t);
        if (lane == 0) sm[0] = t;
    }
    __syncthreads();
    const float inv = 1.0f / sm[0];

    uint2 hv;
    hv.x = pack2(__float2half(v0.x * inv), __float2half(v0.y * inv));
    hv.y = pack2(__float2half(v0.z * inv), __float2half(v0.w * inv));
    ((uint2*)(ah + base))[tid] = hv;
    hv.x = pack2(__float2half(v1.x * inv), __float2half(v1.y * inv));
    hv.y = pack2(__float2half(v1.z * inv), __float2half(v1.w * inv));
    ((uint2*)(ah + base))[tid + 256] = hv;
}

// ---------------------------------------------------------------------------
extern "C" void kernel_launch(void* const* d_in, const int* in_sizes, int n_in,
                              void* d_out, int out_size)
{
    const float* x  = (const float*)d_in[0];
    const float* Wq = (const float*)d_in[1];
    const float* bq = (const float*)d_in[2];
    const float* Wk = (const float*)d_in[3];
    const float* bk = (const float*)d_in[4];
    const float* Wv = (const float*)d_in[5];
    const float* bv = (const float*)d_in[6];
    const float* Wm = (const float*)d_in[7];
    const float* bm = (const float*)d_in[8];
    float* out = (float*)d_out;
    (void)bq;  // bq enters scores only via terms constant along the softmax axis

    __half *xh, *xl, *Wqh, *Wql, *Wkh, *Wkl, *Wvh, *Wvl, *Wmh, *Wml;
    __half *M2h, *M2l, *Zh, *Zl, *Vh, *VWt, *ah;
    float *Vf, *S, *wv, *w;
    cudaGetSymbolAddress((void**)&xh, g_xh);   cudaGetSymbolAddress((void**)&xl, g_xl);
    cudaGetSymbolAddress((void**)&Wqh, g_Wqh); cudaGetSymbolAddress((void**)&Wql, g_Wql);
    cudaGetSymbolAddress((void**)&Wkh, g_Wkh); cudaGetSymbolAddress((void**)&Wkl, g_Wkl);
    cudaGetSymbolAddress((void**)&Wvh, g_Wvh); cudaGetSymbolAddress((void**)&Wvl, g_Wvl);
    cudaGetSymbolAddress((void**)&Wmh, g_Wmh); cudaGetSymbolAddress((void**)&Wml, g_Wml);
    cudaGetSymbolAddress((void**)&M2h, g_M2h); cudaGetSymbolAddress((void**)&M2l, g_M2l);
    cudaGetSymbolAddress((void**)&Zh, g_Zh);   cudaGetSymbolAddress((void**)&Zl, g_Zl);
    cudaGetSymbolAddress((void**)&Vf, g_Vf);
    cudaGetSymbolAddress((void**)&Vh, g_Vh);
    cudaGetSymbolAddress((void**)&VWt, g_VWt);
    cudaGetSymbolAddress((void**)&ah, g_ah);
    cudaGetSymbolAddress((void**)&S, g_S);
    cudaGetSymbolAddress((void**)&wv, g_wv);   cudaGetSymbolAddress((void**)&w, g_w);

    cudaFuncSetAttribute(gemm_mma<3, 1, 0, false>,
                         cudaFuncAttributeMaxDynamicSharedMemorySize, SMEM_BYTES);
    cudaFuncSetAttribute(gemm_mma<3, 0, 0, false>,
                         cudaFuncAttributeMaxDynamicSharedMemorySize, SMEM_BYTES);
    cudaFuncSetAttribute(gemm_mma<1, 0, 1, false>,
                         cudaFuncAttributeMaxDynamicSharedMemorySize, SMEM_BYTES);
    cudaFuncSetAttribute(gemm_mma<1, 2, 0, false>,
                         cudaFuncAttributeMaxDynamicSharedMemorySize, SMEM_BYTES);
    cudaFuncSetAttribute(gemm_mma<1, 0, 1, true>,
                         cudaFuncAttributeMaxDynamicSharedMemorySize, SMEM_BYTES);

    const long long nX = (long long)BN_TOT * D_EMB;
    const long long nW = (long long)D_EMB * D_EMB;

    // ---- fork side stream ----
    cudaEventRecord(g_e0, 0);
    cudaStreamWaitEvent(g_sB, g_e0, 0);

    // side stream: split x FIRST (concurrent with main's Wqk split + M2)
    split_kernel<<<(unsigned)((nX / 4 + 255) / 256), 256, 0, g_sB>>>(x, xh, xl, nX / 4);
    cudaEventRecord(g_eX, g_sB);

    // side stream: weight transposes + bias matvecs
    {
        dim3 g(D_EMB / 32, D_EMB / 32, 1), b(32, 8);
        tsplit_kernel<<<g, b, 0, g_sB>>>(Wv, Wvh, Wvl, D_EMB, D_EMB);
        tsplit_kernel<<<g, b, 0, g_sB>>>(Wm, Wmh, Wml, D_EMB, D_EMB);
    }
    matvec_kernel<<<D_EMB / 8, 256, 0, g_sB>>>(Wq, bk, wv);
    matvec_kernel<<<BN_TOT / 8, 256, 0, g_sB>>>(x, wv, w);
    cudaEventRecord(g_eW, g_sB);

    // side stream: V projection (1-MMA) -> fp32 Vf (with bv), hi split,
    // then VWt[e,i] = sum_d Wm^T[e,d] * V[i,d]  (1-MMA)
    {
        dim3 g(D_EMB / 256, BN_TOT / 128, 1);
        gemm_mma<1, 0, 1, false><<<g, 256, SMEM_BYTES, g_sB>>>(
            xh, nullptr, Wvh, nullptr, bv, Vf, nullptr, nullptr,
            D_EMB, D_EMB, 0, 0, 0);
    }
    split_hi_kernel<<<(unsigned)((nX / 4 + 255) / 256), 256, 0, g_sB>>>(Vf, Vh, nX / 4);
    {
        dim3 g(N_SEQ / 256, D_EMB / 128, N_BATCH);
        gemm_mma<1, 2, 0, false><<<g, 256, SMEM_BYTES, g_sB>>>(
            Wmh, nullptr, Vh, nullptr, nullptr, nullptr, VWt, nullptr,
            N_SEQ, D_EMB, 0, (long long)N_SEQ * D_EMB,
            (long long)D_EMB * N_SEQ);
    }
    cudaEventRecord(g_eV, g_sB);

    // main stream: Wq+Wk split (fused) -> M2 (no dependence on x!)
    split2_kernel<<<(unsigned)((2 * nW / 4 + 255) / 256), 256>>>(
        Wq, Wqh, Wql, Wk, Wkh, Wkl, nW / 4);
    {
        dim3 g(D_EMB / 256, D_EMB / 128, 1);
        gemm_mma<3, 1, 0, false><<<g, 256, SMEM_BYTES>>>(
            Wqh, Wql, Wkh, Wkl, nullptr, nullptr, M2h, M2l, D_EMB, D_EMB, 0, 0, 0);
    }

    // main stream: Z = x @ M (needs xh/xl from side stream)
    cudaStreamWaitEvent(0, g_eX, 0);
    {
        dim3 g(D_EMB / 256, BN_TOT / 128, 1);
        gemm_mma<3, 1, 0, false><<<g, 256, SMEM_BYTES>>>(
            xh, xl, M2h, M2l, nullptr, nullptr, Zh, Zl, D_EMB, D_EMB, 0, 0, 0);
    }

    // main stream: S (single batched launch)
    {
        dim3 g(N_SEQ / 256, N_SEQ / 128, N_BATCH);
        gemm_mma<3, 0, 0, false><<<g, 256, SMEM_BYTES>>>(
            Zh, Zl, xh, xl, nullptr, S, nullptr, nullptr,
            N_SEQ, D_EMB,
            (long long)N_SEQ * D_EMB, (long long)N_SEQ * D_EMB,
            (long long)N_SEQ * N_SEQ);
    }

    // softmax (needs w), then single fused tail GEMM
    cudaStreamWaitEvent(0, g_eW, 0);
    softmax_split<<<BN_TOT, 256>>>(S, w, ah);

    cudaStreamWaitEvent(0, g_eV, 0);
    {
        dim3 g(D_EMB / 256, N_SEQ / 128, N_BATCH);
        gemm_mma<1, 0, 1, true><<<g, 256, SMEM_BYTES>>>(
            ah, nullptr, VWt, nullptr, bm, out, nullptr, nullptr,
            D_EMB, N_SEQ,
            (long long)N_SEQ * N_SEQ, (long long)D_EMB * N_SEQ,
            (long long)N_SEQ * D_EMB);
    }
}